// round 1
// baseline (speedup 1.0000x reference)
#include <cuda_runtime.h>
#include <math.h>

#define IMN 4096
#define NPIX (IMN*IMN)
#define MED_RANK 8388607u   /* (NPIX-1)/2 */

// ---------------- device scratch (no allocations allowed) ----------------
__device__ float    g_R[NPIX];          // Harris response
__device__ unsigned g_hist[8192];       // radix-select histogram (reused per pass)
__device__ unsigned g_prefix;           // accumulated key prefix
__device__ unsigned g_rank;             // remaining rank
__device__ float    g_med;              // selected median value

// monotonic float<->uint order transform
__device__ __forceinline__ unsigned f2u(float f) {
    unsigned u = __float_as_uint(f);
    return (u & 0x80000000u) ? ~u : (u | 0x80000000u);
}
__device__ __forceinline__ float u2f(unsigned u) {
    return (u & 0x80000000u) ? __uint_as_float(u & 0x7fffffffu)
                             : __uint_as_float(~u);
}

// ---------------- init ----------------
__global__ void k_init() {
    int t = threadIdx.x;
    for (int b = t; b < 8192; b += 256) g_hist[b] = 0u;
    if (t == 0) { g_prefix = 0u; g_rank = MED_RANK; g_med = 0.0f; }
}

// ---------------- fused Sobel + products + 7x7 Gaussian -> R ----------------
// 32x32 output tile, halo 4 (1 sobel + 3 gaussian). 256 threads.
__global__ __launch_bounds__(256) void k_R(const float* __restrict__ x,
                                           const float* __restrict__ gk) {
    __shared__ float sx [40][41];
    __shared__ float sIx[38][39];
    __shared__ float sIy[38][39];
    __shared__ float sh [3][38][33];

    const int tid = threadIdx.x;
    const int bx = blockIdx.x * 32, by = blockIdx.y * 32;

    // 1D gaussian factors from provided 2D kernel: w[k] = g2[3][k]/sqrt(g2[3][3])
    float winv = rsqrtf(gk[24]);
    float w[7];
#pragma unroll
    for (int k = 0; k < 7; k++) w[k] = gk[21 + k] * winv;

    // stage 0: load x tile with zero padding
    for (int i = tid; i < 40 * 40; i += 256) {
        int r = i / 40, c = i % 40;
        int gy = by - 4 + r, gx = bx - 4 + c;
        float v = 0.0f;
        if ((unsigned)gy < IMN && (unsigned)gx < IMN) v = x[gy * IMN + gx];
        sx[r][c] = v;
    }
    __syncthreads();

    // stage 1: Sobel (cross-correlation) on 38x38 region; zero outside image
    for (int i = tid; i < 38 * 38; i += 256) {
        int r = i / 38, c = i % 38;
        int gy = by - 3 + r, gx = bx - 3 + c;
        float ix = 0.0f, iy = 0.0f;
        if ((unsigned)gy < IMN && (unsigned)gx < IMN) {
            float a  = sx[r    ][c], b = sx[r    ][c + 1], cc = sx[r    ][c + 2];
            float d  = sx[r + 1][c],                       f  = sx[r + 1][c + 2];
            float g  = sx[r + 2][c], h = sx[r + 2][c + 1], i2 = sx[r + 2][c + 2];
            ix = (cc - a) + 2.0f * (f - d) + (i2 - g);
            iy = (g + 2.0f * h + i2) - (a + 2.0f * b + cc);
        }
        sIx[r][c] = ix;
        sIy[r][c] = iy;
    }
    __syncthreads();

    // stage 2: horizontal 7-tap gaussian of the 3 products
    for (int i = tid; i < 38 * 32; i += 256) {
        int r = i / 32, c = i % 32;
        float s0 = 0.0f, s1 = 0.0f, s2 = 0.0f;
#pragma unroll
        for (int k = 0; k < 7; k++) {
            float a = sIx[r][c + k], b = sIy[r][c + k], wk = w[k];
            s0 = fmaf(wk, a * a, s0);
            s1 = fmaf(wk, b * b, s1);
            s2 = fmaf(wk, a * b, s2);
        }
        sh[0][r][c] = s0; sh[1][r][c] = s1; sh[2][r][c] = s2;
    }
    __syncthreads();

    // stage 3: vertical 7-tap gaussian + Harris response
    const int tx = tid & 31, ty = tid >> 5;
#pragma unroll
    for (int j = 0; j < 4; j++) {
        int r = ty * 4 + j;
        float a0 = 0.0f, a1 = 0.0f, a2 = 0.0f;
#pragma unroll
        for (int k = 0; k < 7; k++) {
            float wk = w[k];
            a0 = fmaf(wk, sh[0][r + k][tx], a0);
            a1 = fmaf(wk, sh[1][r + k][tx], a1);
            a2 = fmaf(wk, sh[2][r + k][tx], a2);
        }
        float tr = a0 + a1;
        float R  = (a0 * a1 - a2 * a2) - 0.05f * tr * tr;
        g_R[(by + r) * IMN + (bx + tx)] = R;
    }
}

// ---------------- radix-select histogram pass ----------------
__global__ __launch_bounds__(256) void k_hist(unsigned mask, int shift, unsigned binmask) {
    __shared__ unsigned h[8192];
    for (int b = threadIdx.x; b < 8192; b += 256) h[b] = 0u;
    __syncthreads();

    unsigned pref = g_prefix;
    const float4* R4 = (const float4*)g_R;
    const int n4 = NPIX / 4;
    const int stride = gridDim.x * blockDim.x;
    for (int i = blockIdx.x * blockDim.x + threadIdx.x; i < n4; i += stride) {
        float4 v = R4[i];
        unsigned u;
        u = f2u(v.x); if ((u & mask) == pref) atomicAdd(&h[(u >> shift) & binmask], 1u);
        u = f2u(v.y); if ((u & mask) == pref) atomicAdd(&h[(u >> shift) & binmask], 1u);
        u = f2u(v.z); if ((u & mask) == pref) atomicAdd(&h[(u >> shift) & binmask], 1u);
        u = f2u(v.w); if ((u & mask) == pref) atomicAdd(&h[(u >> shift) & binmask], 1u);
    }
    __syncthreads();
    for (int b = threadIdx.x; b < 8192; b += 256) {
        unsigned c = h[b];
        if (c) atomicAdd(&g_hist[b], c);
    }
}

// ---------------- radix-select bin selection (single block) ----------------
__global__ __launch_bounds__(256) void k_select(int nbins, int shift, int isFinal) {
    __shared__ unsigned partial[256];
    __shared__ unsigned prefx[256];
    const int tid = threadIdx.x;
    const int per = (nbins + 255) / 256;
    const unsigned rank = g_rank;
    const unsigned pref = g_prefix;

    int b0 = tid * per;
    int b1 = min(nbins, b0 + per);
    unsigned s = 0u;
    for (int b = b0; b < b1; b++) s += g_hist[b];
    partial[tid] = s;
    __syncthreads();
    if (tid == 0) {
        unsigned run = 0u;
        for (int i = 0; i < 256; i++) { prefx[i] = run; run += partial[i]; }
    }
    __syncthreads();

    unsigned before = prefx[tid];
    if (s > 0u && rank >= before && rank < before + s) {
        unsigned run = before;
        for (int b = b0; b < b1; b++) {
            unsigned c = g_hist[b];
            if (rank < run + c) {
                unsigned np = pref | ((unsigned)b << shift);
                g_prefix = np;
                g_rank   = rank - run;
                if (isFinal) g_med = u2f(np);
                break;
            }
            run += c;
        }
    }
    __syncthreads();
    for (int b = tid; b < nbins; b += 256) g_hist[b] = 0u;
}

// ---------------- fused threshold + 7x7 NMS maxpool + mask ----------------
__global__ __launch_bounds__(256) void k_nms(float* __restrict__ out) {
    __shared__ float sr[38][40];
    __shared__ float hm[38][33];
    const int tid = threadIdx.x;
    const int bx = blockIdx.x * 32, by = blockIdx.y * 32;
    const float med = g_med;

    for (int i = tid; i < 38 * 38; i += 256) {
        int r = i / 38, c = i % 38;
        int gy = by - 3 + r, gx = bx - 3 + c;
        float v = -INFINITY;
        if ((unsigned)gy < IMN && (unsigned)gx < IMN) {
            float q = g_R[gy * IMN + gx];
            v = (q < med) ? 0.0f : q;
        }
        sr[r][c] = v;
    }
    __syncthreads();

    for (int i = tid; i < 38 * 32; i += 256) {
        int r = i / 32, c = i % 32;
        float m = sr[r][c];
#pragma unroll
        for (int k = 1; k < 7; k++) m = fmaxf(m, sr[r][c + k]);
        hm[r][c] = m;
    }
    __syncthreads();

    const int tx = tid & 31, ty = tid >> 5;
#pragma unroll
    for (int j = 0; j < 4; j++) {
        int r = ty * 4 + j;
        float m = hm[r][tx];
#pragma unroll
        for (int k = 1; k < 7; k++) m = fmaxf(m, hm[r + k][tx]);
        float ctr = sr[r + 3][tx + 3];
        out[(by + r) * IMN + (bx + tx)] = (ctr == m) ? ctr : 0.0f;
    }
}

// ---------------- launch ----------------
extern "C" void kernel_launch(void* const* d_in, const int* in_sizes, int n_in,
                              void* d_out, int out_size) {
    const float* x  = (const float*)d_in[0];
    const float* gk = (const float*)d_in[1];
    float* out = (float*)d_out;

    dim3 grid(IMN / 32, IMN / 32);

    k_init<<<1, 256>>>();
    k_R<<<grid, 256>>>(x, gk);

    // pass 1: bits [31:19]
    k_hist<<<1184, 256>>>(0x00000000u, 19, 8191u);
    k_select<<<1, 256>>>(8192, 19, 0);
    // pass 2: bits [18:6]
    k_hist<<<1184, 256>>>(0xFFF80000u, 6, 8191u);
    k_select<<<1, 256>>>(8192, 6, 0);
    // pass 3: bits [5:0]
    k_hist<<<1184, 256>>>(0xFFFFFFC0u, 0, 63u);
    k_select<<<1, 256>>>(64, 0, 1);

    k_nms<<<grid, 256>>>(out);
}